// round 4
// baseline (speedup 1.0000x reference)
#include <cuda_runtime.h>
#include <cuda_bf16.h>

// Scratch (no allocation allowed).
__device__ double             g_sums[3];
__device__ unsigned long long g_cnts[3];
__device__ float              g_means[3];

// ---------------------------------------------------------------------------
// Kernel 0: zero accumulators (graph replays reuse them).
// ---------------------------------------------------------------------------
__global__ void iwap_zero_kernel() {
    int i = threadIdx.x;
    if (i < 3) {
        g_sums[i]  = 0.0;
        g_cnts[i]  = 0ull;
        g_means[i] = 0.0f;
    }
}

// ---------------------------------------------------------------------------
// Kernel 1: grid-stride reduction (unchanged from R3 — single wave, ~5.15TB/s).
// Only class 0/1 accumulated explicitly; class 2 derived from totals.
// ---------------------------------------------------------------------------
__global__ __launch_bounds__(256)
void iwap_reduce_kernel(const float4* __restrict__ feats4,
                        const int4*  __restrict__ inst4,
                        const float* __restrict__ feats,
                        const int*   __restrict__ inst,
                        int nitems, int npix) {
    float    ptot = 0.f, s0 = 0.f, s1 = 0.f;
    unsigned c0 = 0, c1 = 0, nit = 0;

    const int stride = gridDim.x * blockDim.x;
    for (int i = blockIdx.x * blockDim.x + threadIdx.x; i < nitems; i += stride) {
        int4   cls = __ldg(&inst4[i]);
        float4 a   = __ldcs(&feats4[3 * i + 0]);
        float4 b   = __ldcs(&feats4[3 * i + 1]);
        float4 d   = __ldcs(&feats4[3 * i + 2]);
        float p0 = a.x + a.y + a.z;
        float p1 = a.w + b.x + b.y;
        float p2 = b.z + b.w + d.x;
        float p3 = d.y + d.z + d.w;
        ptot += (p0 + p1) + (p2 + p3);
        s0 += (cls.x == 0) ? p0 : 0.f;  c0 += (cls.x == 0);
        s1 += (cls.x == 1) ? p0 : 0.f;  c1 += (cls.x == 1);
        s0 += (cls.y == 0) ? p1 : 0.f;  c0 += (cls.y == 0);
        s1 += (cls.y == 1) ? p1 : 0.f;  c1 += (cls.y == 1);
        s0 += (cls.z == 0) ? p2 : 0.f;  c0 += (cls.z == 0);
        s1 += (cls.z == 1) ? p2 : 0.f;  c1 += (cls.z == 1);
        s0 += (cls.w == 0) ? p3 : 0.f;  c0 += (cls.w == 0);
        s1 += (cls.w == 1) ? p3 : 0.f;  c1 += (cls.w == 1);
        nit++;
    }

    unsigned ntail = 0;
    if (blockIdx.x == 0 && threadIdx.x == 0) {
        for (int p = nitems * 4; p < npix; p++) {
            int   c  = inst[p];
            float ps = feats[3 * p] + feats[3 * p + 1] + feats[3 * p + 2];
            ptot += ps; ntail++;
            if      (c == 0) { s0 += ps; c0++; }
            else if (c == 1) { s1 += ps; c1++; }
        }
    }

    float    s2 = ptot - s0 - s1;
    unsigned c2 = 4u * nit + ntail - c0 - c1;

    #pragma unroll
    for (int off = 16; off > 0; off >>= 1) {
        s0 += __shfl_down_sync(0xffffffffu, s0, off);
        s1 += __shfl_down_sync(0xffffffffu, s1, off);
        s2 += __shfl_down_sync(0xffffffffu, s2, off);
        c0 += __shfl_down_sync(0xffffffffu, c0, off);
        c1 += __shfl_down_sync(0xffffffffu, c1, off);
        c2 += __shfl_down_sync(0xffffffffu, c2, off);
    }

    __shared__ float    bs[3];
    __shared__ unsigned bc[3];
    if (threadIdx.x < 3) { bs[threadIdx.x] = 0.f; bc[threadIdx.x] = 0u; }
    __syncthreads();
    if ((threadIdx.x & 31) == 0) {
        atomicAdd(&bs[0], s0); atomicAdd(&bs[1], s1); atomicAdd(&bs[2], s2);
        atomicAdd(&bc[0], c0); atomicAdd(&bc[1], c1); atomicAdd(&bc[2], c2);
    }
    __syncthreads();
    if (threadIdx.x < 3) {
        atomicAdd(&g_sums[threadIdx.x], (double)bs[threadIdx.x]);
        atomicAdd(&g_cnts[threadIdx.x], (unsigned long long)bc[threadIdx.x]);
    }
}

// ---------------------------------------------------------------------------
// Kernel 2: finalize means. Count includes the 3 channels (x3).
// ---------------------------------------------------------------------------
__global__ void iwap_finalize_kernel() {
    int c = threadIdx.x;
    if (c < 3) {
        double cnt = 3.0 * (double)g_cnts[c];
        g_means[c] = (cnt > 0.0) ? (float)(g_sums[c] / cnt) : 0.0f;
    }
}

// ---------------------------------------------------------------------------
// Kernel 3: PERSISTENT grid-stride scatter. 1216 blocks (one wave), each loops
// over ~13.5 tiles of 1024 pixels. The next tile's inst4 load is issued right
// after the staging barrier so its ~250cyc L2 latency hides under the current
// tile's 3 coalesced float4 stores. Eliminates ~13 wave transitions.
// Bad-class detection uses __syncthreads_or (replaces the plain barrier).
// ---------------------------------------------------------------------------
__global__ __launch_bounds__(256)
void iwap_scatter_kernel(const int4*  __restrict__ inst4,
                         float4* __restrict__ out4,
                         const int*   __restrict__ inst,
                         const float* __restrict__ feats,
                         float* __restrict__ out,
                         int npix) {
    __shared__ float vmean[1024];

    const int t      = threadIdx.x;
    const int tmod   = t % 3;
    const int ntile  = npix >> 10;               // full 1024-pixel tiles
    const float m0 = g_means[0], m1 = g_means[1], m2 = g_means[2];

    int tile = blockIdx.x;
    int4 v = make_int4(0, 0, 0, 0);
    if (tile < ntile) v = __ldg(&inst4[(tile << 8) + t]);

    while (tile < ntile) {
        const int nextTile = tile + gridDim.x;

        // Stage per-pixel means into smem.
        bool bad = ((unsigned)v.x >= 3u) | ((unsigned)v.y >= 3u) |
                   ((unsigned)v.z >= 3u) | ((unsigned)v.w >= 3u);
        float4 mv;
        mv.x = (v.x == 0) ? m0 : ((v.x == 1) ? m1 : m2);
        mv.y = (v.y == 0) ? m0 : ((v.y == 1) ? m1 : m2);
        mv.z = (v.z == 0) ? m0 : ((v.z == 1) ? m1 : m2);
        mv.w = (v.w == 0) ? m0 : ((v.w == 1) ? m1 : m2);
        *(float4*)&vmean[4 * t] = mv;

        const int anybad = __syncthreads_or((int)bad);   // barrier + detect

        // Prefetch next tile's classes — latency overlaps the stores below.
        int4 vn = make_int4(0, 0, 0, 0);
        if (nextTile < ntile) vn = __ldg(&inst4[(nextTile << 8) + t]);

        // 3 lane-contiguous float4 stores per thread (perfectly coalesced).
        const int j0 = tile * 768;                      // (tile<<8)*3
        #pragma unroll
        for (int k = 0; k < 3; k++) {
            int   idx = (k << 8) + t;                   // float4 idx within tile
            int   plo = (4 * idx) / 3;                  // low pixel of vector
            int   mod = tmod + k;  mod -= (mod >= 3) ? 3 : 0;
            float lo  = vmean[plo];
            float hi  = vmean[plo + 1];                 // plo <= 1022, safe
            float4 r;
            r.x = lo;
            r.y = (mod == 2) ? hi : lo;
            r.z = (mod == 0) ? lo : hi;
            r.w = hi;
            __stcs(&out4[j0 + idx], r);
        }

        if (anybad) {
            // Essentially-impossible path: order after ALL vector stores,
            // then each thread repairs its own 4 pixels.
            __syncthreads();
            if (bad) {
                int base = (tile << 10) + 4 * t;
                int cs[4] = {v.x, v.y, v.z, v.w};
                for (int q = 0; q < 4; q++) {
                    int p = base + q;
                    if ((unsigned)cs[q] >= 3u) {
                        out[3 * p]     = feats[3 * p];
                        out[3 * p + 1] = feats[3 * p + 1];
                        out[3 * p + 2] = feats[3 * p + 2];
                    }
                }
            }
        }

        __syncthreads();                                // smem reuse next iter
        v    = vn;
        tile = nextTile;
    }

    // Tail pixels (npix not divisible by 1024): block 0, scalar.
    if (blockIdx.x == 0) {
        for (int p = (ntile << 10) + t; p < npix; p += blockDim.x) {
            int c = inst[p];
            if ((unsigned)c < 3u) {
                float m = (c == 0) ? m0 : ((c == 1) ? m1 : m2);
                out[3 * p] = m; out[3 * p + 1] = m; out[3 * p + 2] = m;
            } else {
                out[3 * p]     = feats[3 * p];
                out[3 * p + 1] = feats[3 * p + 1];
                out[3 * p + 2] = feats[3 * p + 2];
            }
        }
    }
}

// ---------------------------------------------------------------------------
extern "C" void kernel_launch(void* const* d_in, const int* in_sizes, int n_in,
                              void* d_out, int out_size) {
    const float* feats = (const float*)d_in[0];   // [16,1024,1024,3] f32
    const int*   inst  = (const int*)d_in[1];     // [16,1024,1024,1] i32
    float*       out   = (float*)d_out;

    const int npix   = in_sizes[1];               // 16*1024*1024
    const int nitems = npix >> 2;                 // 4 pixels per reduce item

    const float4* feats4 = (const float4*)feats;
    const int4*   inst4  = (const int4*)inst;
    float4*       out4   = (float4*)out;

    iwap_zero_kernel<<<1, 32>>>();

    const int rblocks = 1216;                     // 8 per SM, single wave
    iwap_reduce_kernel<<<rblocks, 256>>>(feats4, inst4, feats, inst, nitems, npix);

    iwap_finalize_kernel<<<1, 32>>>();

    const int sblocks = 1216;                     // persistent scatter, one wave
    iwap_scatter_kernel<<<sblocks, 256>>>(inst4, out4, inst, feats, out, npix);
}